// round 17
// baseline (speedup 1.0000x reference)
#include <cuda_runtime.h>
#include <cuda_bf16.h>
#include <math.h>
#include <stdint.h>

#define HID 128
#define NL 4
#define TPI 258
#define NTILE_TOT (TPI*4)
#define NHT (NTILE_TOT*2)
#define GRID 152
#define THREADS 512
#define PART 16908288

__device__ unsigned short g_act0[4*(size_t)PART];
__device__ unsigned short g_wimg[NL * 65536];
__device__ float g_sx[256];

__device__ __forceinline__ uint32_t smem_u32(const void* p) {
    uint32_t a;
    asm("{ .reg .u64 t; cvta.to.shared.u64 t, %1; cvt.u32.u64 %0, t; }" : "=r"(a) : "l"(p));
    return a;
}
__device__ __forceinline__ void ldsm4(uint32_t& r0, uint32_t& r1, uint32_t& r2, uint32_t& r3, uint32_t addr) {
    asm volatile("ldmatrix.sync.aligned.m8n8.x4.shared.b16 {%0,%1,%2,%3}, [%4];"
        : "=r"(r0), "=r"(r1), "=r"(r2), "=r"(r3) : "r"(addr));
}
__device__ __forceinline__ void mma16816(float* d, const uint32_t* a, uint32_t b0, uint32_t b1) {
    asm volatile("mma.sync.aligned.m16n8k16.row.col.f32.bf16.bf16.f32 "
        "{%0,%1,%2,%3}, {%4,%5,%6,%7}, {%8,%9}, {%0,%1,%2,%3};"
        : "+f"(d[0]), "+f"(d[1]), "+f"(d[2]), "+f"(d[3])
        : "r"(a[0]), "r"(a[1]), "r"(a[2]), "r"(a[3]), "r"(b0), "r"(b1));
}
#define GBAR(gid) asm volatile("bar.sync %0, 256;" :: "r"((gid) + 1) : "memory")
#define MBAR_INIT(a, c) asm volatile("mbarrier.init.shared.b64 [%0], %1;" :: "r"(a), "r"(c) : "memory")
#define MBAR_EXPECT(a, b) asm volatile("mbarrier.arrive.expect_tx.shared.b64 _, [%0], %1;" :: "r"(a), "r"(b) : "memory")
#define BULK_G2S(dst, src, bytes, mb) asm volatile( \
    "cp.async.bulk.shared::cluster.global.mbarrier::complete_tx::bytes [%0], [%1], %2, [%3];" \
    :: "r"(dst), "l"(src), "r"(bytes), "r"(mb) : "memory")
#define MBAR_WAIT(addr, par) do { \
    asm volatile("{\n\t.reg .pred P;\n\tWAITL_%=:\n\t" \
        "mbarrier.try_wait.parity.shared.b64 P, [%0], %1;\n\t" \
        "@P bra.uni WAITD_%=;\n\tbra.uni WAITL_%=;\n\tWAITD_%=:\n\t}" \
        :: "r"(addr), "r"(par) : "memory"); \
} while(0)

__device__ __forceinline__ float gelu_exact(float v) {
    return 0.5f * v * (1.0f + erff(v * 0.70710678118654752f));
}
__device__ __forceinline__ uint32_t pack_hi2(float a, float b) {
    return __byte_perm(__float_as_uint(a), __float_as_uint(b), 0x7632);
}
__device__ __forceinline__ uint32_t pack_lo2(float a, float b) {
    float ra = a - __uint_as_float(__float_as_uint(a) & 0xffff0000u);
    float rb = b - __uint_as_float(__float_as_uint(b) & 0xffff0000u);
    __nv_bfloat162 p = __floats2bfloat162_rn(ra, rb);
    return *reinterpret_cast<uint32_t*>(&p);
}
__device__ __forceinline__ void decode_ctile(int tt, int& r, int& x0) {
    if (tt < 254)      { r = 1 + (tt >> 1); x0 = (tt & 1) << 7; }
    else if (tt < 256) { r = 0;             x0 = (tt - 254) << 7; }
    else               { r = 128;           x0 = (tt - 256) << 7; }
}

__device__ __forceinline__ void mma_chunk(
    float (&acc)[4][4], uint32_t aBank, uint32_t bSlot,
    uint32_t arowb, const uint32_t (&brow)[2],
    uint32_t a_c16, uint32_t b_c16, uint32_t xm)
{
    #pragma unroll
    for (int ks = 0; ks < 4; ks++) {
        uint32_t acb = ((uint32_t)(ks * 32) + a_c16) ^ xm;
        uint32_t bcb = ((uint32_t)(ks * 32) + b_c16) ^ xm;
        uint32_t af[4], bh[2][4], bl[2][4];
        ldsm4(af[0], af[1], af[2], af[3], aBank + arowb + acb);
        #pragma unroll
        for (int np = 0; np < 2; np++) {
            ldsm4(bh[np][0], bh[np][1], bh[np][2], bh[np][3], bSlot + brow[np] + bcb);
            ldsm4(bl[np][0], bl[np][1], bl[np][2], bl[np][3], bSlot + 16384u + brow[np] + bcb);
        }
        #pragma unroll
        for (int np = 0; np < 2; np++) {
            mma16816(acc[np * 2],     af, bh[np][0], bh[np][1]);
            mma16816(acc[np * 2 + 1], af, bh[np][2], bh[np][3]);
        }
        #pragma unroll
        for (int np = 0; np < 2; np++) {
            mma16816(acc[np * 2],     af, bl[np][0], bl[np][1]);
            mma16816(acc[np * 2 + 1], af, bl[np][2], bl[np][3]);
        }
        ldsm4(af[0], af[1], af[2], af[3], aBank + 4096u + arowb + acb);
        #pragma unroll
        for (int np = 0; np < 2; np++) {
            mma16816(acc[np * 2],     af, bh[np][0], bh[np][1]);
            mma16816(acc[np * 2 + 1], af, bh[np][2], bh[np][3]);
        }
    }
}

#define SM_B    65536u
#define SM_BIAS 196608u
#define SM_RED  204800u
#define SM_DYN  208896

__global__ void prep_w_kernel(const float* __restrict__ wr,
                              const float* __restrict__ wi,
                              const float* __restrict__ cw,
                              unsigned short* __restrict__ wimg)
{
    int idx = blockIdx.x * blockDim.x + threadIdx.x;
    int l = idx >> 15;
    int rem = idx & 32767;
    int sel = rem >> 14;
    int rem2 = rem & 16383;
    int kc2 = rem2 >> 13;
    int rem3 = rem2 & 8191;
    int o = rem3 >> 6;
    int kl = rem3 & 63;
    int k = kc2 * 64 + kl;
    const float* wsel = (sel ? wi : wr) + (size_t)l * 16384;
    float v = 0.5f * (cw[(size_t)l * 16384 + o * 128 + k] + wsel[k * 128 + o]);
    uint32_t u = __float_as_uint(v);
    float hf = __uint_as_float(u & 0xffff0000u);
    float lo = v - hf;
    uint32_t off = (uint32_t)o * 128 + kl * 2;
    off ^= (off >> 3) & 0x70;
    size_t base = (size_t)(l * 4 + sel * 2 + kc2) * 16384;
    wimg[base + (off >> 1)] = (unsigned short)(u >> 16);
    __nv_bfloat16 lb = __float2bfloat16_rn(lo);
    wimg[base + 8192 + (off >> 1)] = __bfloat16_as_ushort(lb);
}

__global__ void prep_sx_kernel(float* __restrict__ sx)
{
    int x = threadIdx.x;
    double s = 0.0;
    if (x) {
        double th = M_PI * (double)x / 128.0;
        s = sin(63.5 * th) * sin(64.0 * th) / sin(0.5 * th);
    }
    sx[x] = (float)(-s / 128.0);
}

__global__ void in_kernel(const float* __restrict__ x,
                          const float* __restrict__ w,
                          const float* __restrict__ bias,
                          unsigned short* __restrict__ act)
{
    int gid = blockIdx.x * blockDim.x + threadIdx.x;
    int slot = gid >> 5;
    int c4 = (gid & 31) << 2;
    int t = slot >> 7, m = slot & 127;
    int b = t / TPI, tt = t - b * TPI;
    int r, x0;
    decode_ctile(tt, r, x0);
    int xc = x0 + m;
    int rf = (256 - r) & 255, xf = (256 - xc) & 255;
    const float* xb = x + (size_t)b * 196608;
    int ip = r * 256 + xc, iq = rf * 256 + xf;
    float xp0 = __ldg(xb + ip), xp1 = __ldg(xb + ip + 65536), xp2 = __ldg(xb + ip + 131072);
    float xq0 = __ldg(xb + iq), xq1 = __ldg(xb + iq + 65536), xq2 = __ldg(xb + iq + 131072);
    float4 w0 = __ldg((const float4*)(w + c4));
    float4 w1 = __ldg((const float4*)(w + 128 + c4));
    float4 w2 = __ldg((const float4*)(w + 256 + c4));
    float4 bb = __ldg((const float4*)(bias + c4));
    float gp0 = gelu_exact(xp0 * w0.x + xp1 * w1.x + xp2 * w2.x + bb.x);
    float gp1 = gelu_exact(xp0 * w0.y + xp1 * w1.y + xp2 * w2.y + bb.y);
    float gp2 = gelu_exact(xp0 * w0.z + xp1 * w1.z + xp2 * w2.z + bb.z);
    float gp3 = gelu_exact(xp0 * w0.w + xp1 * w1.w + xp2 * w2.w + bb.w);
    float gf0 = gelu_exact(xq0 * w0.x + xq1 * w1.x + xq2 * w2.x + bb.x);
    float gf1 = gelu_exact(xq0 * w0.y + xq1 * w1.y + xq2 * w2.y + bb.y);
    float gf2 = gelu_exact(xq0 * w0.z + xq1 * w1.z + xq2 * w2.z + bb.z);
    float gf3 = gelu_exact(xq0 * w0.w + xq1 * w1.w + xq2 * w2.w + bb.w);
    float s0 = gp0 + gf0, s1 = gp1 + gf1, s2 = gp2 + gf2, s3 = gp3 + gf3;
    float d0 = gp0 - gf0, d1 = gp1 - gf1, d2 = gp2 - gf2, d3 = gp3 - gf3;

    int ht = slot >> 6, mm = slot & 63;
    int g = mm >> 5, rp = mm & 31;
    int nn = c4 & 63;
    int bk = c4 >> 6;
    uint32_t woff = (uint32_t)rp * 128u + (((uint32_t)nn * 2u) ^ ((uint32_t)(rp & 7) << 4));
    char* base = (char*)act + (size_t)ht * 65536 + (size_t)g * 32768
               + (size_t)bk * 8192 + woff;
    uint2 v;
    v.x = pack_hi2(s0, s1); v.y = pack_hi2(s2, s3); *(uint2*)(base)         = v;
    v.x = pack_lo2(s0, s1); v.y = pack_lo2(s2, s3); *(uint2*)(base + 4096)  = v;
    v.x = pack_hi2(d0, d1); v.y = pack_hi2(d2, d3); *(uint2*)(base + 16384) = v;
    v.x = pack_lo2(d0, d1); v.y = pack_lo2(d2, d3); *(uint2*)(base + 20480) = v;
}

__global__ void __launch_bounds__(THREADS, 1) fused_kernel(
    const unsigned short* __restrict__ actIn,
    const char* __restrict__ wimgB,
    const float* __restrict__ cbp, const float* __restrict__ brp,
    const float* __restrict__ bip, const float* __restrict__ lowp,
    const float* __restrict__ lobp, float* __restrict__ gout)
{
    extern __shared__ char dsm_raw[];
    __shared__ __align__(8) uint64_t s_mbar[6];
    __shared__ int s_cnt[4];
    __shared__ int s_cntA[2];
    uint32_t raw = smem_u32(dsm_raw);
    uint32_t sbase = (raw + 127) & ~127u;
    char* sm = dsm_raw + (sbase - raw);

    int tid = threadIdx.x, wid = tid >> 5, lane = tid & 31;
    int g = wid >> 3;
    int widg = wid & 7;
    int tidg = tid & 255;
    int ng = widg & 3;
    int ms = widg >> 2;

    uint32_t mbB = smem_u32(&s_mbar[0]);
    uint32_t mbA = smem_u32(&s_mbar[4]) + (uint32_t)g * 8;
    uint32_t gA  = sbase + (uint32_t)g * 32768u;
    char* gAp = sm + (size_t)g * 32768u;

    int nloc = (NHT - blockIdx.x + GRID - 1) / GRID;

    if (tid == 0) {
        #pragma unroll
        for (int j = 0; j < 4; j++) { s_cnt[j] = 0; MBAR_INIT(mbB + j * 8, 1); }
        s_cntA[0] = 0; s_cntA[1] = 0;
        uint32_t mbA0 = smem_u32(&s_mbar[4]);
        MBAR_INIT(mbA0, 1); MBAR_INIT(mbA0 + 8, 1);
        const char* asrc = (const char*)actIn + (size_t)blockIdx.x * 65536;
        MBAR_EXPECT(mbA0, 32768u);
        BULK_G2S(sbase, asrc, 32768u, mbA0);
        MBAR_EXPECT(mbA0 + 8, 32768u);
        BULK_G2S(sbase + 32768u, asrc + 32768, 32768u, mbA0 + 8);
        #pragma unroll
        for (int c = 0; c < 4; c++) {
            MBAR_EXPECT(mbB + c * 8, 32768u);
            BULK_G2S(sbase + SM_B + (uint32_t)c * 32768u, wimgB + (size_t)c * 32768, 32768u, mbB + c * 8);
        }
    }
    {
        float* bf = (float*)(sm + SM_BIAS);
        bf[tid]        = __ldg(cbp + tid);
        bf[512 + tid]  = __ldg(brp + tid);
        bf[1024 + tid] = __ldg(bip + tid);
        if (tid < 128) bf[1536 + tid] = __ldg(lowp + tid);
    }
    __syncthreads();

    int grp = lane >> 3, lr = lane & 7;
    uint32_t xm = (uint32_t)(lr << 4);
    uint32_t a_c16 = (uint32_t)((grp >> 1) << 4);
    uint32_t b_c16 = (uint32_t)((grp & 1) << 4);
    uint32_t arowb = (uint32_t)(ms * 16 + lr + ((grp & 1) << 3)) * 128u;
    uint32_t brow[2];
    #pragma unroll
    for (int np = 0; np < 2; np++)
        brow[np] = (uint32_t)(ng * 32 + np * 16 + lr + ((grp >> 1) << 3)) * 128u;

    float* redg = (float*)(sm + SM_RED) + g * 256;

    for (int i = 0; i < nloc; i++) {
        int ht = blockIdx.x + i * GRID;
        int t = ht >> 1, hx = ht & 1;
        int b = t / TPI, tt = t - b * TPI;
        int r, x0;
        decode_ctile(tt, r, x0);
        int x0h = x0 + hx * 64;
        bool row0 = (r == 0);
        bool lastTile = (i + 1 == nloc);

        MBAR_WAIT(mbA, i & 1);

        #pragma unroll 1
        for (int l = 0; l < 4; l++) {
            float accP[4][4], accQ[4][4];
            #pragma unroll
            for (int nt = 0; nt < 4; nt++)
                #pragma unroll
                for (int z = 0; z < 4; z++) { accP[nt][z] = 0.0f; accQ[nt][z] = 0.0f; }

            int parB = l & 1;
            bool noRefill = lastTile && (l == 3);
            int srcChunk = ((l + 1) & 3) * 4;

            #pragma unroll
            for (int c = 0; c < 4; c++) {
                uint32_t mbc = mbB + (uint32_t)c * 8;
                MBAR_WAIT(mbc, parB);
                mma_chunk((c < 2) ? accP : accQ,
                          gA + (uint32_t)c * 8192u,
                          sbase + SM_B + (uint32_t)c * 32768u,
                          arowb, brow, a_c16, b_c16, xm);
                if (lane == 0) {
                    int old = atomicAdd(&s_cnt[c], 1);
                    if (old == 15) {
                        s_cnt[c] = 0;
                        if (!noRefill) {
                            MBAR_EXPECT(mbc, 32768u);
                            BULK_G2S(sbase + SM_B + (uint32_t)c * 32768u,
                                     wimgB + (size_t)(srcChunk + c) * 32768,
                                     32768u, mbc);
                        }
                    }
                }
            }
            if (l == 3 && lane == 0) {
                int old = atomicAdd(&s_cntA[g], 1);
                if (old == 7) {
                    s_cntA[g] = 0;
                    if (!lastTile) {
                        MBAR_EXPECT(mbA, 32768u);
                        BULK_G2S(gA, (const char*)actIn + (size_t)(ht + GRID) * 65536
                                     + (size_t)g * 32768, 32768u, mbA);
                    }
                }
            }

            GBAR(g);

            const float* cbS = (const float*)(sm + SM_BIAS) + l * 128;
            const float* brS = (const float*)(sm + SM_BIAS) + 512 + l * 128;
            const float* biS = (const float*)(sm + SM_BIAS) + 1024 + l * 128;

            if (l < 3) {
                #pragma unroll
                for (int rh = 0; rh < 2; rh++) {
                    int rp = ms * 16 + (lane >> 2) + rh * 8;
                    int p = g * 32 + rp;
                    int xc = x0h + p;
                    int xf = (256 - xc) & 255;
                    float sxp = row0 ? __ldg(&g_sx[xc]) : 0.0f;
                    float sxf = row0 ? __ldg(&g_sx[xf]) : 0.0f;
                    uint32_t rowoff = (uint32_t)rp * 128u;
                    uint32_t swz = (uint32_t)(rp & 7) << 4;
                    #pragma unroll
                    for (int nt = 0; nt < 4; nt++) {
                        int n = ng * 32 + nt * 8 + (lane & 3) * 2;
                        float P0 = accP[nt][rh * 2], P1 = accP[nt][rh * 2 + 1];
                        float Q0 = accQ[nt][rh * 2], Q1 = accQ[nt][rh * 2 + 1];
                        float c0 = cbS[n], c1 = cbS[n + 1];
                        float up0 = P0 + Q0 + c0, up1 = P1 + Q1 + c1;
                        float uf0 = P0 - Q0 + c0, uf1 = P1 - Q1 + c1;
                        if (row0) {
                            float b0 = biS[n], b1 = biS[n + 1];
                            up0 += b0 * sxp; up1 += b1 * sxp;
                            uf0 += b0 * sxf; uf1 += b1 * sxf;
                            if (xc == 0) {
                                up0 += brS[n]; up1 += brS[n + 1];
                                uf0 += brS[n]; uf1 += brS[n + 1];
                            }
                        }
                        float gp0 = gelu_exact(up0), gp1 = gelu_exact(up1);
                        float gf0 = gelu_exact(uf0), gf1 = gelu_exact(uf1);
                        float s0 = gp0 + gf0, s1 = gp1 + gf1;
                        float d0 = gp0 - gf0, d1 = gp1 - gf1;
                        uint32_t boff = (uint32_t)(n >> 6) * 8192u + rowoff
                                      + ((((uint32_t)n & 63u) * 2u) ^ swz);
                        *(uint32_t*)(gAp + boff)          = pack_hi2(s0, s1);
                        *(uint32_t*)(gAp + boff + 4096u)  = pack_lo2(s0, s1);
                        *(uint32_t*)(gAp + boff + 16384u) = pack_hi2(d0, d1);
                        *(uint32_t*)(gAp + boff + 20480u) = pack_lo2(d0, d1);
                    }
                }
                GBAR(g);
            } else {
                const float* lowS = (const float*)(sm + SM_BIAS) + 1536;
                #pragma unroll
                for (int rh = 0; rh < 2; rh++) {
                    int rp = ms * 16 + (lane >> 2) + rh * 8;
                    int p = g * 32 + rp;
                    int xc = x0h + p;
                    int xf = (256 - xc) & 255;
                    float sxp = row0 ? __ldg(&g_sx[xc]) : 0.0f;
                    float sxf = row0 ? __ldg(&g_sx[xf]) : 0.0f;
                    float pp = 0.0f, pf = 0.0f;
                    #pragma unroll
                    for (int nt = 0; nt < 4; nt++) {
                        int n = ng * 32 + nt * 8 + (lane & 3) * 2;
                        float P0 = accP[nt][rh * 2], P1 = accP[nt][rh * 2 + 1];
                        float Q0 = accQ[nt][rh * 2], Q1 = accQ[nt][rh * 2 + 1];
                        float c0 = cbS[n], c1 = cbS[n + 1];
                        float up0 = P0 + Q0 + c0, up1 = P1 + Q1 + c1;
                        float uf0 = P0 - Q0 + c0, uf1 = P1 - Q1 + c1;
                        if (row0) {
                            float b0 = biS[n], b1 = biS[n + 1];
                            up0 += b0 * sxp; up1 += b1 * sxp;
                            uf0 += b0 * sxf; uf1 += b1 * sxf;
                            if (xc == 0) {
                                up0 += brS[n]; up1 += brS[n + 1];
                                uf0 += brS[n]; uf1 += brS[n + 1];
                            }
                        }
                        pp += gelu_exact(up0) * lowS[n] + gelu_exact(up1) * lowS[n + 1];
                        pf += gelu_exact(uf0) * lowS[n] + gelu_exact(uf1) * lowS[n + 1];
                    }
                    pp += __shfl_xor_sync(0xffffffffu, pp, 1);
                    pp += __shfl_xor_sync(0xffffffffu, pp, 2);
                    pf += __shfl_xor_sync(0xffffffffu, pf, 1);
                    pf += __shfl_xor_sync(0xffffffffu, pf, 2);
                    if ((lane & 3) == 0) {
                        redg[ng * 32 + rp]       = pp;
                        redg[128 + ng * 32 + rp] = pf;
                    }
                }
                GBAR(g);
                if (tidg < 32) {
                    float lob = __ldg(lobp);
                    int rp = tidg;
                    float sp = redg[rp] + redg[32 + rp] + redg[64 + rp] + redg[96 + rp];
                    float sf = redg[128 + rp] + redg[160 + rp] + redg[192 + rp] + redg[224 + rp];
                    int p = g * 32 + rp;
                    int xc = x0h + p, xf = (256 - xc) & 255, rf = (256 - r) & 255;
                    gout[(size_t)b * 65536 + r * 256 + xc]  = gelu_exact(sp + lob);
                    gout[(size_t)b * 65536 + rf * 256 + xf] = gelu_exact(sf + lob);
                }
                GBAR(g);
            }
        }
    }
}

extern "C" void kernel_launch(void* const* d_in, const int* in_sizes, int n_in,
                              void* d_out, int out_size)
{
    const float* x   = (const float*)d_in[0];
    const float* liw = (const float*)d_in[1];
    const float* lib = (const float*)d_in[2];
    const float* wr  = (const float*)d_in[3];
    const float* wi  = (const float*)d_in[4];
    const float* br  = (const float*)d_in[5];
    const float* bi  = (const float*)d_in[6];
    const float* cw  = (const float*)d_in[7];
    const float* cb  = (const float*)d_in[8];
    const float* low = (const float*)d_in[9];
    const float* lob = (const float*)d_in[10];
    float* out = (float*)d_out;

    unsigned short *a0, *wimg;
    float* sx;
    cudaGetSymbolAddress((void**)&a0, g_act0);
    cudaGetSymbolAddress((void**)&wimg, g_wimg);
    cudaGetSymbolAddress((void**)&sx, g_sx);

    cudaFuncSetAttribute(fused_kernel, cudaFuncAttributeMaxDynamicSharedMemorySize, SM_DYN);

    prep_w_kernel<<<512, 256>>>(wr, wi, cw, wimg);
    prep_sx_kernel<<<1, 256>>>(sx);
    in_kernel<<<NTILE_TOT * 128 * 32 / 256, 256>>>(x, liw, lib, a0);

    fused_kernel<<<GRID, THREADS, SM_DYN>>>(
        a0, (const char*)wimg, cb, br, bi, low, lob, out);
}